// round 5
// baseline (speedup 1.0000x reference)
#include <cuda_runtime.h>
#include <cuda_fp16.h>
#include <cstdint>
#include <math.h>

#define NC      64
#define DHEAD   128
#define BATCHB  512
#define COLS    8192
#define KC      64
#define NCHUNKS 8
#define PADH    72          // halfs per smem row: 144B stride, conflict-free phases
#define ROWB    144         // bytes per smem row
#define A_STAGE (DHEAD * ROWB)          // 18432
#define B_STAGE (2 * DHEAD * ROWB)      // 36864
#define SMEM_DYN (2 * A_STAGE + 2 * B_STAGE)  // 110592

// q^2 (scaled by 256) transposed: [gram][col][b], fp16. 16.8 MB (L2-resident)
__device__ __half g_Xt[2ULL * COLS * BATCHB];
__device__ float g_acc[4]; // [0]=dot(q_a,q_b), [1]=sum sqrt gram a (pairs i<c, x256), [2]=gram b

__device__ __forceinline__ float fsqrt_fast(float x) {
    float r; asm("sqrt.approx.f32 %0, %1;" : "=f"(r) : "f"(x)); return r;
}
__device__ __forceinline__ uint32_t smem_u32(const void* p) {
    uint32_t a;
    asm("{ .reg .u64 t; cvta.to.shared.u64 t, %1; cvt.u32.u64 %0, t; }" : "=r"(a) : "l"(p));
    return a;
}
#define CP16(dst, src) \
    asm volatile("cp.async.cg.shared.global [%0], [%1], 16;" :: "r"(dst), "l"(src))
#define CP_COMMIT() asm volatile("cp.async.commit_group;" ::: "memory")
#define CP_WAIT1()  asm volatile("cp.async.wait_group 1;"  ::: "memory")
#define CP_WAIT0()  asm volatile("cp.async.wait_group 0;"  ::: "memory")

// ---------------- kernel 0 ----------------
__global__ void k_zero() { if (threadIdx.x < 4) g_acc[threadIdx.x] = 0.0f; }

// ---------------- kernel 1: softmax + q^2 fp16 transposed + self-sim dot ----------------
__global__ void k_softmax(const float* __restrict__ emb) {
    const int c    = blockIdx.y;
    const int b0   = blockIdx.x * 16;
    const int w    = threadIdx.x >> 5;
    const int lane = threadIdx.x & 31;

    __shared__ __align__(16) __half sm_t[2][DHEAD][16];
    __shared__ float dotred[16];

    const int b = b0 + w;
    const float* pa = emb + (size_t)b * COLS + c * DHEAD;
    const float* pb = emb + (size_t)(b + BATCHB) * COLS + c * DHEAD;

    float xa[4], xb[4];
#pragma unroll
    for (int p = 0; p < 4; ++p) { xa[p] = pa[lane + 32 * p]; xb[p] = pb[lane + 32 * p]; }

    float ma = fmaxf(fmaxf(xa[0], xa[1]), fmaxf(xa[2], xa[3]));
    float mb = fmaxf(fmaxf(xb[0], xb[1]), fmaxf(xb[2], xb[3]));
#pragma unroll
    for (int off = 16; off > 0; off >>= 1) {
        ma = fmaxf(ma, __shfl_xor_sync(0xFFFFFFFFu, ma, off));
        mb = fmaxf(mb, __shfl_xor_sync(0xFFFFFFFFu, mb, off));
    }
    float ea[4], eb[4], sa = 0.f, sb = 0.f;
#pragma unroll
    for (int p = 0; p < 4; ++p) {
        ea[p] = __expf(xa[p] - ma); sa += ea[p];
        eb[p] = __expf(xb[p] - mb); sb += eb[p];
    }
#pragma unroll
    for (int off = 16; off > 0; off >>= 1) {
        sa += __shfl_xor_sync(0xFFFFFFFFu, sa, off);
        sb += __shfl_xor_sync(0xFFFFFFFFu, sb, off);
    }
    const float ia = 16.0f / sa, ib = 16.0f / sb;   // fold x16 into q
    float dot = 0.f;
#pragma unroll
    for (int p = 0; p < 4; ++p) {
        float qa = ea[p] * ia;
        float qb = eb[p] * ib;
        dot += qa * qb;                              // 256 * qa*qb
        sm_t[0][lane + 32 * p][w] = __float2half_rn(qa * qa);   // 256*q^2
        sm_t[1][lane + 32 * p][w] = __float2half_rn(qb * qb);
    }
#pragma unroll
    for (int off = 16; off > 0; off >>= 1)
        dot += __shfl_xor_sync(0xFFFFFFFFu, dot, off);
    if (lane == 0) dotred[w] = dot;
    __syncthreads();
    if (threadIdx.x == 0) {
        float s = 0.f;
#pragma unroll
        for (int k = 0; k < 16; ++k) s += dotred[k];
        atomicAdd(&g_acc[0], s * (1.0f / 256.0f));
    }
    const int tid = threadIdx.x;
    const int g = tid >> 8;
    const int d = (tid >> 1) & 127;
    const int h = tid & 1;
    uint4 v = *(const uint4*)&sm_t[g][d][h * 8];
    __half* dst = g_Xt + (size_t)g * COLS * BATCHB
                + (size_t)(c * DHEAD + d) * BATCHB + (b0 + h * 8);
    *(uint4*)dst = v;
}

// ---------------- kernel 2: 128x256 Gram macro-tile, cp.async double-buffered ----------------
// Tile (g, i): rows = cluster i (128), cols = clusters {2g, 2g+1} (256). i in [0, 2g+1).
// 8 warps: wm = wid&1 (2 x 64 rows), wn = wid>>1 (4 x 64 cols). Warp tile 64x64.
__global__ void __launch_bounds__(256, 1) k_gram() {
    extern __shared__ __align__(16) char dsm[];
    __shared__ float wsum[8];

    const uint32_t sbase = smem_u32(dsm);
    const int tid  = threadIdx.x;
    const int wid  = tid >> 5;
    const int lane = tid & 31;

    // tile decode: t = g*g + i
    const int t = blockIdx.x;
    int g = (int)sqrtf((float)t);
    while (g * g > t) --g;
    while ((g + 1) * (g + 1) <= t) ++g;
    const int i = t - g * g;                 // 0 .. 2g
    const bool skipL = (i == 2 * g);         // mask diagonal block (left 128 cols)
    const int gram = blockIdx.y;

    const __half* xg = g_Xt + (size_t)gram * COLS * BATCHB;
    const __half* gA = xg + (size_t)i * DHEAD * BATCHB;          // 128 rows
    const __half* gB = xg + (size_t)(2 * g) * DHEAD * BATCHB;    // 256 rows

    const int wm = wid & 1, wn = wid >> 1;
    const int wr = wm * 64, wc = wn * 64;
    const int g4 = lane >> 2;       // 0..7
    const int tg = lane & 3;        // 0..3

    float acc[4][8][4];
#pragma unroll
    for (int a = 0; a < 4; ++a)
#pragma unroll
        for (int b = 0; b < 8; ++b)
#pragma unroll
            for (int c2 = 0; c2 < 4; ++c2) acc[a][b][c2] = 0.f;

    // ---- async chunk loader ----
    auto load_chunk = [&](int st, int ch) {
        const uint32_t aoff = sbase + st * A_STAGE;
        const uint32_t boff = sbase + 2 * A_STAGE + st * B_STAGE;
#pragma unroll
        for (int it = 0; it < 4; ++it) {
            const int u = tid + it * 256;
            const int r = u >> 3, seg = u & 7;
            CP16(aoff + r * ROWB + seg * 16,
                 gA + (size_t)r * BATCHB + ch * KC + seg * 8);
        }
#pragma unroll
        for (int it = 0; it < 8; ++it) {
            const int u = tid + it * 256;
            const int r = u >> 3, seg = u & 7;
            CP16(boff + r * ROWB + seg * 16,
                 gB + (size_t)r * BATCHB + ch * KC + seg * 8);
        }
        CP_COMMIT();
    };

    load_chunk(0, 0);

#pragma unroll 1
    for (int ch = 0; ch < NCHUNKS; ++ch) {
        const int st = ch & 1;
        if (ch + 1 < NCHUNKS) { load_chunk(st ^ 1, ch + 1); CP_WAIT1(); }
        else                  { CP_WAIT0(); }
        __syncthreads();

        const __half* pA = (const __half*)(dsm + st * A_STAGE);
        const __half* pB = (const __half*)(dsm + 2 * A_STAGE + st * B_STAGE);

#pragma unroll
        for (int ks = 0; ks < 4; ++ks) {
            const int k0 = ks * 16;
            uint32_t afr[4][4];
#pragma unroll
            for (int rm = 0; rm < 4; ++rm) {
                const int rb = wr + rm * 16;
                afr[rm][0] = *(const uint32_t*)&pA[(rb + g4     ) * PADH + k0 + tg * 2    ];
                afr[rm][1] = *(const uint32_t*)&pA[(rb + g4 + 8 ) * PADH + k0 + tg * 2    ];
                afr[rm][2] = *(const uint32_t*)&pA[(rb + g4     ) * PADH + k0 + tg * 2 + 8];
                afr[rm][3] = *(const uint32_t*)&pA[(rb + g4 + 8 ) * PADH + k0 + tg * 2 + 8];
            }
#pragma unroll
            for (int cn = 0; cn < 8; ++cn) {
                const int nb = wc + cn * 8;
                const uint32_t b0 = *(const uint32_t*)&pB[(nb + g4) * PADH + k0 + tg * 2    ];
                const uint32_t b1 = *(const uint32_t*)&pB[(nb + g4) * PADH + k0 + tg * 2 + 8];
#pragma unroll
                for (int rm = 0; rm < 4; ++rm) {
                    asm volatile(
                        "mma.sync.aligned.m16n8k16.row.col.f32.f16.f16.f32 "
                        "{%0,%1,%2,%3}, {%4,%5,%6,%7}, {%8,%9}, {%0,%1,%2,%3};"
                        : "+f"(acc[rm][cn][0]), "+f"(acc[rm][cn][1]),
                          "+f"(acc[rm][cn][2]), "+f"(acc[rm][cn][3])
                        : "r"(afr[rm][0]), "r"(afr[rm][1]), "r"(afr[rm][2]), "r"(afr[rm][3]),
                          "r"(b0), "r"(b1));
                }
            }
        }
        __syncthreads();
    }

    // epilogue: sum sqrt over valid columns (mask diagonal block when i == 2g)
    float lsum = 0.f;
#pragma unroll
    for (int cn = 0; cn < 8; ++cn) {
        const bool valid = !skipL || (wc + cn * 8 >= 128);
        if (valid) {
#pragma unroll
            for (int rm = 0; rm < 4; ++rm)
#pragma unroll
                for (int c2 = 0; c2 < 4; ++c2)
                    lsum += fsqrt_fast(acc[rm][cn][c2]);
        }
    }
#pragma unroll
    for (int off = 16; off > 0; off >>= 1)
        lsum += __shfl_xor_sync(0xFFFFFFFFu, lsum, off);
    if (lane == 0) wsum[wid] = lsum;
    __syncthreads();
    if (tid == 0) {
        float s = 0.f;
#pragma unroll
        for (int k = 0; k < 8; ++k) s += wsum[k];
        atomicAdd(&g_acc[1 + gram], s);
    }
}

// ---------------- kernel 3: finalize ----------------
__global__ void k_final(float* __restrict__ out) {
    // operands carry 256x -> G entries 65536x -> sqrt 256x.
    // raw_g (i!=j) = 2 * (i<j sum) = 2*acc/256; cluster = -(raw_a+raw_b)/(2*scale)
    const float scale = (float)(NC * NC - NC) * sqrtf((float)BATCHB);
    const float self = -g_acc[0] / (float)(BATCHB * NC);
    const float clus = -(2.0f * (g_acc[1] + g_acc[2]) / 256.0f) / (2.0f * scale);
    out[0] = self + clus;
}

extern "C" void kernel_launch(void* const* d_in, const int* in_sizes, int n_in,
                              void* d_out, int out_size) {
    const float* emb = (const float*)d_in[0];
    float* out = (float*)d_out;
    cudaFuncSetAttribute(k_gram, cudaFuncAttributeMaxDynamicSharedMemorySize, SMEM_DYN);
    k_zero<<<1, 32>>>();
    k_softmax<<<dim3(32, 64), 512>>>(emb);
    k_gram<<<dim3(1024, 2), 256, SMEM_DYN>>>();
    k_final<<<1, 1>>>(out);
}